// round 1
// baseline (speedup 1.0000x reference)
#include <cuda_runtime.h>
#include <math.h>
#include <float.h>

// ----------------------------------------------------------------------------
// GATv2 x2 + mean-pool + classifier, dense-pair formulation.
// N=201 nodes, E=40200 edges (+201 self loops), D=1024 = 8 heads x 128 ch.
// ----------------------------------------------------------------------------

#define NN   201
#define EE   40200
#define DD   1024
#define HH   8
#define CC   128
#define NPJ  224            // padded j-dimension for score/alpha/count rows
#define NPAD 204            // padded node rows for XL (score kernel may touch row 201)

// -------- scratch (device globals; no allocation allowed) -------------------
__device__ __align__(16) float g_XL[NPAD * DD];
__device__ __align__(16) float g_XR[NPAD * DD];
__device__ __align__(16) float g_H [NPAD * DD];   // layer-1 output / layer-2 input
__device__ __align__(16) float g_H2[NPAD * DD];   // layer-2 output
__device__ __align__(16) float g_A [HH * NN * NPJ]; // attention weights (alpha * count)
__device__ int   g_cnt[NN * NPJ];
__device__ int   g_estride;                        // 1 = int32 edge buffer, 2 = int64
__device__ __align__(16) float g_avg[DD];

// ---------------------------------------------------------------------------
// init: detect edge dtype stride, reset count matrix (diag = 1 for self loops)
// ---------------------------------------------------------------------------
__global__ void k_init(const int* __restrict__ eb) {
    int idx = blockIdx.x * blockDim.x + threadIdx.x;
    if (idx == 0) {
        int st = 2;  // assume int64 (low word = value, high word = 0)
        for (int e = 0; e < 64; e++) {
            if (eb[2 * e + 1] != 0) { st = 1; break; }
        }
        g_estride = st;
    }
    if (idx < NN * NPJ) {
        int r = idx / NPJ, c = idx - r * NPJ;
        g_cnt[idx] = (r == c && r < NN) ? 1 : 0;
    }
}

__global__ void k_count(const int* __restrict__ eb) {
    int e = blockIdx.x * blockDim.x + threadIdx.x;
    if (e < EE) {
        int st  = g_estride;
        int src = eb[e * st];
        int dst = eb[(EE + e) * st];
        atomicAdd(&g_cnt[dst * NPJ + src], 1);
    }
}

// ---------------------------------------------------------------------------
// GEMM: O[m][n] = sum_k X[m][k] * W[n][k] + b[n]     (M=201, N=1024, K=1024)
// z=0 -> (Wl, bl) -> g_XL ; z=1 -> (Wr, br) -> g_XR.  X==nullptr -> use g_H.
// 64x64 tile, BK=16, 256 threads, 4x4 microtile, register prefetch.
// ---------------------------------------------------------------------------
__global__ void __launch_bounds__(256) k_gemm(
    const float* __restrict__ Xin,
    const float* __restrict__ Wl, const float* __restrict__ bl,
    const float* __restrict__ Wr, const float* __restrict__ br)
{
    const float* X = Xin ? Xin : g_H;
    const float* W = blockIdx.z ? Wr : Wl;
    const float* b = blockIdx.z ? br : bl;
    float*       O = blockIdx.z ? g_XR : g_XL;

    __shared__ float As[16][64];
    __shared__ float Bs[16][64];

    const int tid  = threadIdx.x;
    const int tx   = tid & 15;
    const int ty   = tid >> 4;
    const int m0   = blockIdx.x * 64;
    const int n0   = blockIdx.y * 64;
    const int lrow = tid >> 2;         // 0..63
    const int lq   = (tid & 3) << 2;   // 0,4,8,12

    const int  gm     = m0 + lrow;
    const bool mvalid = (gm < NN);
    const float* xrow = X + gm * DD;
    const float* wrow = W + (n0 + lrow) * DD;

    float acc[4][4];
#pragma unroll
    for (int i = 0; i < 4; i++)
#pragma unroll
        for (int j = 0; j < 4; j++) acc[i][j] = 0.f;

    float4 xa = mvalid ? *(const float4*)(xrow + lq) : make_float4(0, 0, 0, 0);
    float4 wb = *(const float4*)(wrow + lq);

    for (int k0 = 0; k0 < DD; k0 += 16) {
        As[lq + 0][lrow] = xa.x; As[lq + 1][lrow] = xa.y;
        As[lq + 2][lrow] = xa.z; As[lq + 3][lrow] = xa.w;
        Bs[lq + 0][lrow] = wb.x; Bs[lq + 1][lrow] = wb.y;
        Bs[lq + 2][lrow] = wb.z; Bs[lq + 3][lrow] = wb.w;
        __syncthreads();

        if (k0 + 16 < DD) {  // prefetch next tile while computing this one
            xa = mvalid ? *(const float4*)(xrow + k0 + 16 + lq) : make_float4(0, 0, 0, 0);
            wb = *(const float4*)(wrow + k0 + 16 + lq);
        }

#pragma unroll
        for (int k = 0; k < 16; k++) {
            float4 a4 = *(const float4*)&As[k][ty << 2];
            float4 b4 = *(const float4*)&Bs[k][tx << 2];
            float av[4] = {a4.x, a4.y, a4.z, a4.w};
            float bv[4] = {b4.x, b4.y, b4.z, b4.w};
#pragma unroll
            for (int i = 0; i < 4; i++)
#pragma unroll
                for (int j = 0; j < 4; j++)
                    acc[i][j] = fmaf(av[i], bv[j], acc[i][j]);
        }
        __syncthreads();
    }

#pragma unroll
    for (int i = 0; i < 4; i++) {
        int m = m0 + (ty << 2) + i;
        if (m < NN) {
#pragma unroll
            for (int j = 0; j < 4; j++) {
                int n = n0 + (tx << 2) + j;
                O[m * DD + n] = acc[i][j] + b[n];
            }
        }
    }
}

// ---------------------------------------------------------------------------
// Score + segment softmax. One block per destination node i.
// Warp w <-> head h. Two source nodes j per warp pass (16-lane halves),
// each lane covers 8 channels.  Writes alpha*count into g_A[h][i][j].
// ---------------------------------------------------------------------------
__global__ void __launch_bounds__(256) k_score(const float* __restrict__ att) {
    const int i    = blockIdx.x;
    const int h    = threadIdx.x >> 5;
    const int lane = threadIdx.x & 31;
    const int half = lane >> 4;
    const int sub  = lane & 15;
    const int c0   = (h << 7) + (sub << 3);

    __shared__ float s_s[HH][NPJ];
    __shared__ int   cnt_s[NPJ];

    const float4 xr0 = *(const float4*)(g_XR + i * DD + c0);
    const float4 xr1 = *(const float4*)(g_XR + i * DD + c0 + 4);
    const float4 at0 = *(const float4*)(att + c0);
    const float4 at1 = *(const float4*)(att + c0 + 4);

    for (int j = threadIdx.x; j < NN; j += 256) cnt_s[j] = g_cnt[i * NPJ + j];
    __syncthreads();

    for (int jp = 0; jp < NN; jp += 2) {
        int j = jp + half;                       // j==201 touches padded row: harmless
        const float* xp = g_XL + j * DD + c0;
        float4 xl0 = *(const float4*)xp;
        float4 xl1 = *(const float4*)(xp + 4);
        float s = 0.f;
        {
            float t, l;
            t = xl0.x + xr0.x; l = fmaxf(t, 0.f) + 0.2f * fminf(t, 0.f); s = fmaf(at0.x, l, s);
            t = xl0.y + xr0.y; l = fmaxf(t, 0.f) + 0.2f * fminf(t, 0.f); s = fmaf(at0.y, l, s);
            t = xl0.z + xr0.z; l = fmaxf(t, 0.f) + 0.2f * fminf(t, 0.f); s = fmaf(at0.z, l, s);
            t = xl0.w + xr0.w; l = fmaxf(t, 0.f) + 0.2f * fminf(t, 0.f); s = fmaf(at0.w, l, s);
            t = xl1.x + xr1.x; l = fmaxf(t, 0.f) + 0.2f * fminf(t, 0.f); s = fmaf(at1.x, l, s);
            t = xl1.y + xr1.y; l = fmaxf(t, 0.f) + 0.2f * fminf(t, 0.f); s = fmaf(at1.y, l, s);
            t = xl1.z + xr1.z; l = fmaxf(t, 0.f) + 0.2f * fminf(t, 0.f); s = fmaf(at1.z, l, s);
            t = xl1.w + xr1.w; l = fmaxf(t, 0.f) + 0.2f * fminf(t, 0.f); s = fmaf(at1.w, l, s);
        }
        s += __shfl_xor_sync(0xffffffffu, s, 8);
        s += __shfl_xor_sync(0xffffffffu, s, 4);
        s += __shfl_xor_sync(0xffffffffu, s, 2);
        s += __shfl_xor_sync(0xffffffffu, s, 1);
        if (sub == 0) s_s[h][j] = s;
    }
    __syncwarp();

    // segment softmax for head h (warp h owns its smem row)
    float mx = -FLT_MAX;
    for (int j = lane; j < NN; j += 32)
        if (cnt_s[j] > 0) mx = fmaxf(mx, s_s[h][j]);
    for (int o = 16; o; o >>= 1) mx = fmaxf(mx, __shfl_xor_sync(0xffffffffu, mx, o));

    float ds = 0.f;
    for (int j = lane; j < NN; j += 32)
        ds += (float)cnt_s[j] * __expf(s_s[h][j] - mx);
    for (int o = 16; o; o >>= 1) ds += __shfl_xor_sync(0xffffffffu, ds, o);

    float inv = 1.f / (ds + 1e-16f);
    for (int j = lane; j < NN; j += 32)
        g_A[(h * NN + i) * NPJ + j] = (float)cnt_s[j] * __expf(s_s[h][j] - mx) * inv;
}

// ---------------------------------------------------------------------------
// Aggregation: OUT[i][h][c] = sum_j A[h][i][j] * XL[j][h][c] + bias, opt. ReLU.
// Block = (i-tile of 8, head). Warp w <-> i-tile row, lane <-> channel quad.
// ---------------------------------------------------------------------------
__global__ void __launch_bounds__(256) k_agg(const float* __restrict__ bias,
                                             int relu, int dst_sel) {
    float*    OUT  = dst_sel ? g_H2 : g_H;
    const int h    = blockIdx.y;
    const int i0   = blockIdx.x * 8;
    const int warp = threadIdx.x >> 5;
    const int lane = threadIdx.x & 31;

    __shared__ float  al[8][NPJ];
    __shared__ float4 xs[32][32];

    for (int idx = threadIdx.x; idx < 8 * NPJ; idx += 256) {
        int ii = idx / NPJ, j = idx - ii * NPJ;
        int i = i0 + ii;
        al[ii][j] = (i < NN && j < NN) ? g_A[(h * NN + i) * NPJ + j] : 0.f;
    }

    float4 acc = make_float4(0, 0, 0, 0);
    for (int j0 = 0; j0 < NN; j0 += 32) {
        __syncthreads();
        for (int idx = threadIdx.x; idx < 1024; idx += 256) {
            int jj = idx >> 5, cq = idx & 31;
            int j  = j0 + jj;
            xs[jj][cq] = (j < NN)
                ? *(const float4*)(g_XL + j * DD + (h << 7) + (cq << 2))
                : make_float4(0, 0, 0, 0);
        }
        __syncthreads();
#pragma unroll
        for (int jj = 0; jj < 32; jj++) {
            float  a = al[warp][j0 + jj];
            float4 x = xs[jj][lane];
            acc.x = fmaf(a, x.x, acc.x);
            acc.y = fmaf(a, x.y, acc.y);
            acc.z = fmaf(a, x.z, acc.z);
            acc.w = fmaf(a, x.w, acc.w);
        }
    }

    int i = i0 + warp;
    if (i < NN) {
        float4 bb = *(const float4*)(bias + (h << 7) + (lane << 2));
        float4 o;
        o.x = acc.x + bb.x; o.y = acc.y + bb.y;
        o.z = acc.z + bb.z; o.w = acc.w + bb.w;
        if (relu) {
            o.x = fmaxf(o.x, 0.f); o.y = fmaxf(o.y, 0.f);
            o.z = fmaxf(o.z, 0.f); o.w = fmaxf(o.w, 0.f);
        }
        *(float4*)(OUT + i * DD + (h << 7) + (lane << 2)) = o;
    }
}

// ---------------------------------------------------------------------------
// Pooling: avg[d] = sum_i w_i * H2[i][d],  w_i = 1/300 (i<200), 1/3 (i==200)
// ---------------------------------------------------------------------------
__global__ void k_pool() {
    int d = blockIdx.x * blockDim.x + threadIdx.x;  // 8 x 128 = 1024
    float s = 0.f;
    for (int i = 0; i < NN - 1; i++) s = fmaf(1.f / 300.f, g_H2[i * DD + d], s);
    s = fmaf(1.f / 3.f, g_H2[(NN - 1) * DD + d], s);
    g_avg[d] = s;
}

// ---------------------------------------------------------------------------
// Classifier: out[c] = avg . clfW[c] + clfb[c]
// ---------------------------------------------------------------------------
__global__ void k_clf(const float* __restrict__ W, const float* __restrict__ b,
                      float* __restrict__ out) {
    __shared__ float red0[8], red1[8];
    int tid = threadIdx.x;
    float p0 = 0.f, p1 = 0.f;
    for (int d = tid; d < DD; d += 256) {
        float a = g_avg[d];
        p0 = fmaf(a, W[d], p0);
        p1 = fmaf(a, W[DD + d], p1);
    }
    for (int o = 16; o; o >>= 1) {
        p0 += __shfl_xor_sync(0xffffffffu, p0, o);
        p1 += __shfl_xor_sync(0xffffffffu, p1, o);
    }
    if ((tid & 31) == 0) { red0[tid >> 5] = p0; red1[tid >> 5] = p1; }
    __syncthreads();
    if (tid == 0) {
        float s0 = 0.f, s1 = 0.f;
        for (int w = 0; w < 8; w++) { s0 += red0[w]; s1 += red1[w]; }
        out[0] = s0 + b[0];
        out[1] = s1 + b[1];
    }
}

// ---------------------------------------------------------------------------
extern "C" void kernel_launch(void* const* d_in, const int* in_sizes, int n_in,
                              void* d_out, int out_size) {
    const float* x     = (const float*)d_in[0];
    const int*   ebuf  = (const int*)  d_in[1];
    const float* W1l   = (const float*)d_in[2];
    const float* b1l   = (const float*)d_in[3];
    const float* W1r   = (const float*)d_in[4];
    const float* b1r   = (const float*)d_in[5];
    const float* att1  = (const float*)d_in[6];
    const float* bias1 = (const float*)d_in[7];
    const float* W2l   = (const float*)d_in[8];
    const float* b2l   = (const float*)d_in[9];
    const float* W2r   = (const float*)d_in[10];
    const float* b2r   = (const float*)d_in[11];
    const float* att2  = (const float*)d_in[12];
    const float* bias2 = (const float*)d_in[13];
    const float* clfW  = (const float*)d_in[14];
    const float* clfb  = (const float*)d_in[15];
    float* out = (float*)d_out;

    k_init <<<(NN * NPJ + 255) / 256, 256>>>(ebuf);
    k_count<<<(EE + 255) / 256, 256>>>(ebuf);

    dim3 gg(4, 16, 2);  // ceil(201/64) x (1024/64) x {l,r}

    // layer 1
    k_gemm <<<gg, 256>>>(x, W1l, b1l, W1r, b1r);
    k_score<<<NN, 256>>>(att1);
    k_agg  <<<dim3(26, HH), 256>>>(bias1, /*relu=*/1, /*dst=*/0);

    // layer 2
    k_gemm <<<gg, 256>>>(nullptr, W2l, b2l, W2r, b2r);
    k_score<<<NN, 256>>>(att2);
    k_agg  <<<dim3(26, HH), 256>>>(bias2, /*relu=*/0, /*dst=*/1);

    // pooling + classifier
    k_pool<<<8, 128>>>();
    k_clf <<<1, 256>>>(clfW, clfb, out);
}

// round 2
// speedup vs baseline: 1.4146x; 1.4146x over previous
#include <cuda_runtime.h>
#include <math.h>
#include <float.h>

// ----------------------------------------------------------------------------
// GATv2 x2 + mean-pool + classifier, dense-pair formulation.
// N=201 nodes, E=40200 edges (+201 self loops), D=1024 = 8 heads x 128 ch.
//
// Score algebra: lrelu(t) = 0.6 t + 0.4 |t|  (slope 0.2), so
//   S[h,i,j] = 0.4 * sum_c att[h,c]*|xl[j]+xr[i]| + 0.6*AL[h,j] + 0.6*AR[h,i]
// The AR term is constant over j for fixed (h,i) -> cancels in the softmax.
// ----------------------------------------------------------------------------

#define NN   201
#define EE   40200
#define DD   1024
#define HH   8
#define CC   128
#define NPJ  224            // padded j-dimension (= 7*32) for score/count rows
#define NPAD 204            // padded node rows

// -------- scratch (device globals; no allocation allowed) -------------------
__device__ __align__(16) float g_XL[NPAD * DD];
__device__ __align__(16) float g_XR[NPAD * DD];
__device__ __align__(16) float g_H [NPAD * DD];     // layer-1 out / layer-2 in
__device__ __align__(16) float g_H2[NPAD * DD];     // layer-2 out
__device__ __align__(16) float g_S [HH * NN * NPJ]; // raw scores (AR-shifted)
__device__ int   g_cnt[NN * NPJ];
__device__ int   g_estride;                          // 1 = int32 edges, 2 = int64
__device__ __align__(16) float g_avg[DD];

// ---------------------------------------------------------------------------
// init: detect edge dtype stride, reset count matrix (diag = 1 for self loops)
// ---------------------------------------------------------------------------
__global__ void k_init(const int* __restrict__ eb) {
    int idx = blockIdx.x * blockDim.x + threadIdx.x;
    if (idx == 0) {
        int st = 2;  // assume int64 (low word = value, high word = 0)
        for (int e = 0; e < 64; e++) {
            if (eb[2 * e + 1] != 0) { st = 1; break; }
        }
        g_estride = st;
    }
    if (idx < NN * NPJ) {
        int r = idx / NPJ, c = idx - r * NPJ;
        g_cnt[idx] = (r == c && r < NN) ? 1 : 0;
    }
}

__global__ void k_count(const int* __restrict__ eb) {
    int e = blockIdx.x * blockDim.x + threadIdx.x;
    if (e < EE) {
        int st  = g_estride;
        int src = eb[e * st];
        int dst = eb[(EE + e) * st];
        atomicAdd(&g_cnt[dst * NPJ + src], 1);
    }
}

// ---------------------------------------------------------------------------
// GEMM: O[m][n] = sum_k X[m][k] * W[n][k] + b[n]     (M=201, N=1024, K=1024)
// z=0 -> (Wl, bl) -> g_XL ; z=1 -> (Wr, br) -> g_XR.  X==nullptr -> use g_H.
// ---------------------------------------------------------------------------
__global__ void __launch_bounds__(256) k_gemm(
    const float* __restrict__ Xin,
    const float* __restrict__ Wl, const float* __restrict__ bl,
    const float* __restrict__ Wr, const float* __restrict__ br)
{
    const float* X = Xin ? Xin : g_H;
    const float* W = blockIdx.z ? Wr : Wl;
    const float* b = blockIdx.z ? br : bl;
    float*       O = blockIdx.z ? g_XR : g_XL;

    __shared__ float As[16][64];
    __shared__ float Bs[16][64];

    const int tid  = threadIdx.x;
    const int tx   = tid & 15;
    const int ty   = tid >> 4;
    const int m0   = blockIdx.x * 64;
    const int n0   = blockIdx.y * 64;
    const int lrow = tid >> 2;
    const int lq   = (tid & 3) << 2;

    const int  gm     = m0 + lrow;
    const bool mvalid = (gm < NN);
    const float* xrow = X + gm * DD;
    const float* wrow = W + (n0 + lrow) * DD;

    float acc[4][4];
#pragma unroll
    for (int i = 0; i < 4; i++)
#pragma unroll
        for (int j = 0; j < 4; j++) acc[i][j] = 0.f;

    float4 xa = mvalid ? *(const float4*)(xrow + lq) : make_float4(0, 0, 0, 0);
    float4 wb = *(const float4*)(wrow + lq);

    for (int k0 = 0; k0 < DD; k0 += 16) {
        As[lq + 0][lrow] = xa.x; As[lq + 1][lrow] = xa.y;
        As[lq + 2][lrow] = xa.z; As[lq + 3][lrow] = xa.w;
        Bs[lq + 0][lrow] = wb.x; Bs[lq + 1][lrow] = wb.y;
        Bs[lq + 2][lrow] = wb.z; Bs[lq + 3][lrow] = wb.w;
        __syncthreads();

        if (k0 + 16 < DD) {
            xa = mvalid ? *(const float4*)(xrow + k0 + 16 + lq) : make_float4(0, 0, 0, 0);
            wb = *(const float4*)(wrow + k0 + 16 + lq);
        }

#pragma unroll
        for (int k = 0; k < 16; k++) {
            float4 a4 = *(const float4*)&As[k][ty << 2];
            float4 b4 = *(const float4*)&Bs[k][tx << 2];
            float av[4] = {a4.x, a4.y, a4.z, a4.w};
            float bv[4] = {b4.x, b4.y, b4.z, b4.w};
#pragma unroll
            for (int i = 0; i < 4; i++)
#pragma unroll
                for (int j = 0; j < 4; j++)
                    acc[i][j] = fmaf(av[i], bv[j], acc[i][j]);
        }
        __syncthreads();
    }

#pragma unroll
    for (int i = 0; i < 4; i++) {
        int m = m0 + (ty << 2) + i;
        if (m < NN) {
#pragma unroll
            for (int j = 0; j < 4; j++) {
                int n = n0 + (tx << 2) + j;
                O[m * DD + n] = acc[i][j] + b[n];
            }
        }
    }
}

// ---------------------------------------------------------------------------
// Dense pairwise scores, GEMM-style tiling.
// Block = (i-tile 64, j-tile 64, head). 256 threads, 4x4 microtile.
//   P[i][j]  = sum_c att[h][c] * |xl[j][h][c] + xr[i][h][c]|
//   S[h,i,j] = 0.4*P + 0.6*AL[j],  AL[j] = sum_c att[h][c]*xl[j][h][c]
// ---------------------------------------------------------------------------
__global__ void __launch_bounds__(256) k_score(const float* __restrict__ att) {
    const int h   = blockIdx.z;
    const int i0  = blockIdx.x * 64;
    const int j0  = blockIdx.y * 64;
    const int tid = threadIdx.x;
    const int tx  = tid & 15;
    const int ty  = tid >> 4;
    const int lrow = tid >> 2;
    const int lq   = (tid & 3) << 2;

    __shared__ __align__(16) float att_s[CC];
    __shared__ float AL_s[64];
    __shared__ float alp[64][4];
    __shared__ float As[16][64];   // xr chunk: [c][i]
    __shared__ float Bs[16][64];   // xl chunk: [c][j]

    if (tid < 32) *(float4*)&att_s[tid * 4] = *(const float4*)(att + h * CC + tid * 4);
    __syncthreads();

    // AL[j] partials: 4 threads per j, 32 channels each
    {
        int jj = tid >> 2, part = tid & 3;
        int j  = j0 + jj;
        float s = 0.f;
        if (j < NN) {
            const float4* xp4 = (const float4*)(g_XL + j * DD + h * CC + part * 32);
#pragma unroll
            for (int q = 0; q < 8; q++) {
                float4 xv = xp4[q];
                const float* ap = att_s + part * 32 + q * 4;
                s = fmaf(ap[0], xv.x, s);
                s = fmaf(ap[1], xv.y, s);
                s = fmaf(ap[2], xv.z, s);
                s = fmaf(ap[3], xv.w, s);
            }
        }
        alp[jj][part] = s;
    }
    __syncthreads();
    if (tid < 64) AL_s[tid] = alp[tid][0] + alp[tid][1] + alp[tid][2] + alp[tid][3];
    __syncthreads();

    const int  gi = i0 + lrow;
    const int  gj = j0 + lrow;
    const bool iv = (gi < NN);
    const bool jv = (gj < NN);
    const float* xrp = g_XR + gi * DD + h * CC;
    const float* xlp = g_XL + gj * DD + h * CC;

    float acc[4][4];
#pragma unroll
    for (int i = 0; i < 4; i++)
#pragma unroll
        for (int j = 0; j < 4; j++) acc[i][j] = 0.f;

    float4 ra = iv ? *(const float4*)(xrp + lq) : make_float4(0, 0, 0, 0);
    float4 rb = jv ? *(const float4*)(xlp + lq) : make_float4(0, 0, 0, 0);

    for (int k0 = 0; k0 < CC; k0 += 16) {
        As[lq + 0][lrow] = ra.x; As[lq + 1][lrow] = ra.y;
        As[lq + 2][lrow] = ra.z; As[lq + 3][lrow] = ra.w;
        Bs[lq + 0][lrow] = rb.x; Bs[lq + 1][lrow] = rb.y;
        Bs[lq + 2][lrow] = rb.z; Bs[lq + 3][lrow] = rb.w;
        __syncthreads();

        if (k0 + 16 < CC) {
            ra = iv ? *(const float4*)(xrp + k0 + 16 + lq) : make_float4(0, 0, 0, 0);
            rb = jv ? *(const float4*)(xlp + k0 + 16 + lq) : make_float4(0, 0, 0, 0);
        }

#pragma unroll
        for (int k = 0; k < 16; k++) {
            float4 a4 = *(const float4*)&As[k][ty << 2];
            float4 b4 = *(const float4*)&Bs[k][tx << 2];
            float av[4] = {a4.x, a4.y, a4.z, a4.w};
            float bv[4] = {b4.x, b4.y, b4.z, b4.w};
            float ac = att_s[k0 + k];
#pragma unroll
            for (int i = 0; i < 4; i++)
#pragma unroll
                for (int j = 0; j < 4; j++) {
                    float t = av[i] + bv[j];
                    acc[i][j] = fmaf(ac, fabsf(t), acc[i][j]);
                }
        }
        __syncthreads();
    }

#pragma unroll
    for (int ii = 0; ii < 4; ii++) {
        int i = i0 + (ty << 2) + ii;
        if (i >= NN) continue;
        float* row = g_S + (size_t)(h * NN + i) * NPJ;
#pragma unroll
        for (int jj = 0; jj < 4; jj++) {
            int j = j0 + (tx << 2) + jj;
            if (j < NN)
                row[j] = fmaf(0.4f, acc[ii][jj], 0.6f * AL_s[(tx << 2) + jj]);
        }
    }
}

// ---------------------------------------------------------------------------
// Fused segment-softmax + aggregation.
// Block = (i-tile of 8, head). Warp w owns row i0+w: computes alpha from raw
// scores + counts, then OUT[i][h][c] = sum_j alpha*XL[j][h][c] + bias (+ReLU).
// ---------------------------------------------------------------------------
__global__ void __launch_bounds__(256) k_agg(const float* __restrict__ bias,
                                             int relu, int dst_sel) {
    float*    OUT  = dst_sel ? g_H2 : g_H;
    const int h    = blockIdx.y;
    const int i0   = blockIdx.x * 8;
    const int warp = threadIdx.x >> 5;
    const int lane = threadIdx.x & 31;

    __shared__ float  al[8][NPJ];
    __shared__ float4 xs[32][32];

    // ---- softmax prologue: warp w -> destination row i0+w ----
    {
        int i = i0 + warp;
        if (i < NN) {
            const float* srow = g_S + (size_t)(h * NN + i) * NPJ;
            const int*   crow = g_cnt + i * NPJ;
            float sv[7], cv[7];
            float mx = -FLT_MAX;
#pragma unroll
            for (int t = 0; t < 7; t++) {
                int j = lane + t * 32;
                int c = (j < NN) ? crow[j] : 0;
                float s = (c > 0) ? srow[j] : -1e30f;
                sv[t] = s; cv[t] = (float)c;
                mx = fmaxf(mx, s);
            }
            for (int o = 16; o; o >>= 1) mx = fmaxf(mx, __shfl_xor_sync(0xffffffffu, mx, o));
            float ds = 0.f;
#pragma unroll
            for (int t = 0; t < 7; t++) ds += cv[t] * __expf(sv[t] - mx);
            for (int o = 16; o; o >>= 1) ds += __shfl_xor_sync(0xffffffffu, ds, o);
            float inv = 1.f / (ds + 1e-16f);
#pragma unroll
            for (int t = 0; t < 7; t++)
                al[warp][lane + t * 32] = cv[t] * __expf(sv[t] - mx) * inv;
        } else {
            for (int j = lane; j < NPJ; j += 32) al[warp][j] = 0.f;
        }
    }

    float4 acc = make_float4(0, 0, 0, 0);
    for (int j0 = 0; j0 < NN; j0 += 32) {
        __syncthreads();
        for (int idx = threadIdx.x; idx < 1024; idx += 256) {
            int jj = idx >> 5, cq = idx & 31;
            int j  = j0 + jj;
            xs[jj][cq] = (j < NN)
                ? *(const float4*)(g_XL + j * DD + (h << 7) + (cq << 2))
                : make_float4(0, 0, 0, 0);
        }
        __syncthreads();
#pragma unroll
        for (int jj = 0; jj < 32; jj++) {
            float  a = al[warp][j0 + jj];
            float4 x = xs[jj][lane];
            acc.x = fmaf(a, x.x, acc.x);
            acc.y = fmaf(a, x.y, acc.y);
            acc.z = fmaf(a, x.z, acc.z);
            acc.w = fmaf(a, x.w, acc.w);
        }
    }

    int i = i0 + warp;
    if (i < NN) {
        float4 bb = *(const float4*)(bias + (h << 7) + (lane << 2));
        float4 o;
        o.x = acc.x + bb.x; o.y = acc.y + bb.y;
        o.z = acc.z + bb.z; o.w = acc.w + bb.w;
        if (relu) {
            o.x = fmaxf(o.x, 0.f); o.y = fmaxf(o.y, 0.f);
            o.z = fmaxf(o.z, 0.f); o.w = fmaxf(o.w, 0.f);
        }
        *(float4*)(OUT + i * DD + (h << 7) + (lane << 2)) = o;
    }
}

// ---------------------------------------------------------------------------
// Pooling: avg[d] = sum_i w_i * H2[i][d],  w_i = 1/300 (i<200), 1/3 (i==200)
// ---------------------------------------------------------------------------
__global__ void k_pool() {
    int d = blockIdx.x * blockDim.x + threadIdx.x;
    float s = 0.f;
    for (int i = 0; i < NN - 1; i++) s = fmaf(1.f / 300.f, g_H2[i * DD + d], s);
    s = fmaf(1.f / 3.f, g_H2[(NN - 1) * DD + d], s);
    g_avg[d] = s;
}

// ---------------------------------------------------------------------------
// Classifier: out[c] = avg . clfW[c] + clfb[c]
// ---------------------------------------------------------------------------
__global__ void k_clf(const float* __restrict__ W, const float* __restrict__ b,
                      float* __restrict__ out) {
    __shared__ float red0[8], red1[8];
    int tid = threadIdx.x;
    float p0 = 0.f, p1 = 0.f;
    for (int d = tid; d < DD; d += 256) {
        float a = g_avg[d];
        p0 = fmaf(a, W[d], p0);
        p1 = fmaf(a, W[DD + d], p1);
    }
    for (int o = 16; o; o >>= 1) {
        p0 += __shfl_xor_sync(0xffffffffu, p0, o);
        p1 += __shfl_xor_sync(0xffffffffu, p1, o);
    }
    if ((tid & 31) == 0) { red0[tid >> 5] = p0; red1[tid >> 5] = p1; }
    __syncthreads();
    if (tid == 0) {
        float s0 = 0.f, s1 = 0.f;
        for (int w = 0; w < 8; w++) { s0 += red0[w]; s1 += red1[w]; }
        out[0] = s0 + b[0];
        out[1] = s1 + b[1];
    }
}

// ---------------------------------------------------------------------------
extern "C" void kernel_launch(void* const* d_in, const int* in_sizes, int n_in,
                              void* d_out, int out_size) {
    const float* x     = (const float*)d_in[0];
    const int*   ebuf  = (const int*)  d_in[1];
    const float* W1l   = (const float*)d_in[2];
    const float* b1l   = (const float*)d_in[3];
    const float* W1r   = (const float*)d_in[4];
    const float* b1r   = (const float*)d_in[5];
    const float* att1  = (const float*)d_in[6];
    const float* bias1 = (const float*)d_in[7];
    const float* W2l   = (const float*)d_in[8];
    const float* b2l   = (const float*)d_in[9];
    const float* W2r   = (const float*)d_in[10];
    const float* b2r   = (const float*)d_in[11];
    const float* att2  = (const float*)d_in[12];
    const float* bias2 = (const float*)d_in[13];
    const float* clfW  = (const float*)d_in[14];
    const float* clfb  = (const float*)d_in[15];
    float* out = (float*)d_out;

    k_init <<<(NN * NPJ + 255) / 256, 256>>>(ebuf);
    k_count<<<(EE + 255) / 256, 256>>>(ebuf);

    dim3 gg(4, 16, 2);          // m-tiles x n-tiles x {l,r}
    dim3 gs(4, 4, HH);          // i-tiles x j-tiles x heads

    // layer 1
    k_gemm <<<gg, 256>>>(x, W1l, b1l, W1r, b1r);
    k_score<<<gs, 256>>>(att1);
    k_agg  <<<dim3(26, HH), 256>>>(bias1, /*relu=*/1, /*dst=*/0);

    // layer 2
    k_gemm <<<gg, 256>>>(nullptr, W2l, b2l, W2r, b2r);
    k_score<<<gs, 256>>>(att2);
    k_agg  <<<dim3(26, HH), 256>>>(bias2, /*relu=*/0, /*dst=*/1);

    // pooling + classifier
    k_pool<<<8, 128>>>();
    k_clf <<<1, 256>>>(clfW, clfb, out);
}

// round 4
// speedup vs baseline: 1.8258x; 1.2906x over previous
#include <cuda_runtime.h>
#include <cuda_bf16.h>
#include <mma.h>
#include <math.h>
#include <float.h>
#include <stdint.h>

using namespace nvcuda;

// ----------------------------------------------------------------------------
// GATv2 x2 + mean-pool + classifier, dense-pair formulation.
// N=201 nodes, E=40200 edges (+201 self loops), D=1024 = 8 heads x 128 ch.
// GEMMs on WMMA/HMMA bf16 with hi/lo split x3 (fp32-grade accuracy).
// NOTE: tcgen05 is NOT usable here (harness PTX target is sm_103, no 'a').
// ----------------------------------------------------------------------------

#define NN   201
#define EE   40200
#define DD   1024
#define HH   8
#define CC   128
#define NPJ  224
#define NPAD 204

// -------- scratch (device globals; no allocation allowed) -------------------
__device__ __align__(16) float g_XL[NPAD * DD];
__device__ __align__(16) float g_XR[NPAD * DD];
__device__ __align__(16) float g_H [NPAD * DD];
__device__ __align__(16) float g_H2[NPAD * DD];
__device__ __align__(16) float g_S [HH * NN * NPJ];
__device__ int   g_cnt[NN * NPJ];
__device__ int   g_estride;
__device__ __align__(16) float g_avg[DD];

// ---------------------------------------------------------------------------
// init / edge count
// ---------------------------------------------------------------------------
__global__ void k_init(const int* __restrict__ eb) {
    int idx = blockIdx.x * blockDim.x + threadIdx.x;
    if (idx == 0) {
        int st = 2;  // assume int64 (low word = value, high word = 0)
        for (int e = 0; e < 64; e++)
            if (eb[2 * e + 1] != 0) { st = 1; break; }
        g_estride = st;
    }
    if (idx < NN * NPJ) {
        int r = idx / NPJ, c = idx - r * NPJ;
        g_cnt[idx] = (r == c && r < NN) ? 1 : 0;
    }
}

__global__ void k_count(const int* __restrict__ eb) {
    int e = blockIdx.x * blockDim.x + threadIdx.x;
    if (e < EE) {
        int st  = g_estride;
        int src = eb[e * st];
        int dst = eb[(EE + e) * st];
        atomicAdd(&g_cnt[dst * NPJ + src], 1);
    }
}

// ---------------------------------------------------------------------------
// WMMA bf16 GEMM: O[m][n] = sum_k X[m][k]*W[n][k] + b[n]
// CTA tile 64x64, K staged 32/chunk. hi/lo split, 3 HMMA products.
// grid = (4 m-tiles, 16 n-tiles, 2 sides); 256 threads (8 warps, 32x16 each).
// ---------------------------------------------------------------------------
#define A_LDM 40           // 32 k + 8 pad (bf16 elements)
#define C_LDM 72           // 64 n + 8 pad (fp32 elements)

__global__ void __launch_bounds__(256) k_gemm_mma(
    const float* __restrict__ Xin,
    const float* __restrict__ Wl, const float* __restrict__ bl,
    const float* __restrict__ Wr, const float* __restrict__ br)
{
    __shared__ __align__(16) char sm[64 * C_LDM * 4];  // 18432B >= 4*64*40*2 ? no:
    // bf16 staging needs 4*64*40*2 = 20480B — use a second region
    __shared__ __align__(16) __nv_bfloat16 smh[4 * 64 * A_LDM];

    __nv_bfloat16* Ah = smh;
    __nv_bfloat16* Al = Ah + 64 * A_LDM;
    __nv_bfloat16* Bh = Al + 64 * A_LDM;
    __nv_bfloat16* Bl = Bh + 64 * A_LDM;
    float* Cs = (float*)sm;

    const float* X = Xin ? Xin : g_H;
    const int side = blockIdx.z;
    const float* W = side ? Wr : Wl;
    const float* b = side ? br : bl;
    float*       O = side ? g_XR : g_XL;
    const int m0 = blockIdx.x * 64;
    const int n0 = blockIdx.y * 64;

    const int tid  = threadIdx.x;
    const int wid  = tid >> 5;
    const int wm   = wid >> 2;        // 0..1 -> m offset 0/32
    const int wn   = wid & 3;         // 0..3 -> n offset 0/16/32/48

    wmma::fragment<wmma::accumulator, 16, 16, 16, float> c0, c1;
    wmma::fill_fragment(c0, 0.f);
    wmma::fill_fragment(c1, 0.f);

    // loader mapping: 4 threads per row, 8 k-elements each
    const int  lr = tid >> 2;
    const int  lq = (tid & 3) * 8;
    const bool av = (m0 + lr) < NN;
    const float* arow = X + (size_t)(m0 + lr) * DD + lq;
    const float* brow = W + (size_t)(n0 + lr) * DD + lq;

    for (int kc = 0; kc < DD / 32; kc++) {
        const int kb = kc * 32;
        // ---- stage A chunk (hi/lo) ----
        {
            float4 v0 = av ? *(const float4*)(arow + kb)     : make_float4(0, 0, 0, 0);
            float4 v1 = av ? *(const float4*)(arow + kb + 4) : make_float4(0, 0, 0, 0);
            float vv[8] = {v0.x, v0.y, v0.z, v0.w, v1.x, v1.y, v1.z, v1.w};
            __nv_bfloat16 hi[8], lo[8];
#pragma unroll
            for (int e = 0; e < 8; e++) {
                hi[e] = __float2bfloat16(vv[e]);
                lo[e] = __float2bfloat16(vv[e] - __bfloat162float(hi[e]));
            }
            *(uint4*)(Ah + lr * A_LDM + lq) = *(uint4*)hi;
            *(uint4*)(Al + lr * A_LDM + lq) = *(uint4*)lo;
        }
        // ---- stage B chunk (hi/lo) ----
        {
            float4 v0 = *(const float4*)(brow + kb);
            float4 v1 = *(const float4*)(brow + kb + 4);
            float vv[8] = {v0.x, v0.y, v0.z, v0.w, v1.x, v1.y, v1.z, v1.w};
            __nv_bfloat16 hi[8], lo[8];
#pragma unroll
            for (int e = 0; e < 8; e++) {
                hi[e] = __float2bfloat16(vv[e]);
                lo[e] = __float2bfloat16(vv[e] - __bfloat162float(hi[e]));
            }
            *(uint4*)(Bh + lr * A_LDM + lq) = *(uint4*)hi;
            *(uint4*)(Bl + lr * A_LDM + lq) = *(uint4*)lo;
        }
        __syncthreads();

        // ---- 2 k-steps x (hi*hi + hi*lo + lo*hi) ----
#pragma unroll
        for (int ks = 0; ks < 2; ks++) {
            const int kk = ks * 16;
            wmma::fragment<wmma::matrix_b, 16, 16, 16, __nv_bfloat16, wmma::col_major> fbh, fbl;
            wmma::load_matrix_sync(fbh, Bh + (wn * 16) * A_LDM + kk, A_LDM);
            wmma::load_matrix_sync(fbl, Bl + (wn * 16) * A_LDM + kk, A_LDM);

            wmma::fragment<wmma::matrix_a, 16, 16, 16, __nv_bfloat16, wmma::row_major> fah, fal;
            // m-frag 0
            wmma::load_matrix_sync(fah, Ah + (wm * 32) * A_LDM + kk, A_LDM);
            wmma::load_matrix_sync(fal, Al + (wm * 32) * A_LDM + kk, A_LDM);
            wmma::mma_sync(c0, fah, fbh, c0);
            wmma::mma_sync(c0, fah, fbl, c0);
            wmma::mma_sync(c0, fal, fbh, c0);
            // m-frag 1
            wmma::load_matrix_sync(fah, Ah + (wm * 32 + 16) * A_LDM + kk, A_LDM);
            wmma::load_matrix_sync(fal, Al + (wm * 32 + 16) * A_LDM + kk, A_LDM);
            wmma::mma_sync(c1, fah, fbh, c1);
            wmma::mma_sync(c1, fah, fbl, c1);
            wmma::mma_sync(c1, fal, fbh, c1);
        }
        __syncthreads();
    }

    // ---- epilogue via smem, fused bias ----
    wmma::store_matrix_sync(Cs + (wm * 32) * C_LDM + wn * 16, c0, C_LDM, wmma::mem_row_major);
    wmma::store_matrix_sync(Cs + (wm * 32 + 16) * C_LDM + wn * 16, c1, C_LDM, wmma::mem_row_major);
    __syncthreads();

    const int m = m0 + lr;
    if (m < NN) {
        const int cb = (tid & 3) * 16;
        float* orow = O + (size_t)m * DD + n0 + cb;
        const float* bp = b + n0 + cb;
#pragma unroll
        for (int c4 = 0; c4 < 16; c4 += 4) {
            float4 vv = *(float4*)&Cs[lr * C_LDM + cb + c4];
            float4 bb = *(const float4*)(bp + c4);
            vv.x += bb.x; vv.y += bb.y; vv.z += bb.z; vv.w += bb.w;
            *(float4*)(orow + c4) = vv;
        }
    }
}

// ---------------------------------------------------------------------------
// Dense pairwise scores, GEMM-style tiling (fp32 SIMT).
//   S[h,i,j] = 0.4 * sum_c att|xl_j + xr_i| + 0.6*AL[j]   (AR term cancels)
// ---------------------------------------------------------------------------
__global__ void __launch_bounds__(256) k_score(const float* __restrict__ att) {
    const int h   = blockIdx.z;
    const int i0  = blockIdx.x * 64;
    const int j0  = blockIdx.y * 64;
    const int tid = threadIdx.x;
    const int tx  = tid & 15;
    const int ty  = tid >> 4;
    const int lrow = tid >> 2;
    const int lq   = (tid & 3) << 2;

    __shared__ __align__(16) float att_s[CC];
    __shared__ float AL_s[64];
    __shared__ float alp[64][4];
    __shared__ float As[16][64];
    __shared__ float Bs[16][64];

    if (tid < 32) *(float4*)&att_s[tid * 4] = *(const float4*)(att + h * CC + tid * 4);
    __syncthreads();

    {
        int jj = tid >> 2, part = tid & 3;
        int j  = j0 + jj;
        float s = 0.f;
        if (j < NN) {
            const float4* xp4 = (const float4*)(g_XL + j * DD + h * CC + part * 32);
#pragma unroll
            for (int q = 0; q < 8; q++) {
                float4 xv = xp4[q];
                const float* ap = att_s + part * 32 + q * 4;
                s = fmaf(ap[0], xv.x, s);
                s = fmaf(ap[1], xv.y, s);
                s = fmaf(ap[2], xv.z, s);
                s = fmaf(ap[3], xv.w, s);
            }
        }
        alp[jj][part] = s;
    }
    __syncthreads();
    if (tid < 64) AL_s[tid] = alp[tid][0] + alp[tid][1] + alp[tid][2] + alp[tid][3];
    __syncthreads();

    const int  gi = i0 + lrow;
    const int  gj = j0 + lrow;
    const bool iv = (gi < NN);
    const bool jv = (gj < NN);
    const float* xrp = g_XR + gi * DD + h * CC;
    const float* xlp = g_XL + gj * DD + h * CC;

    float acc[4][4];
#pragma unroll
    for (int i = 0; i < 4; i++)
#pragma unroll
        for (int j = 0; j < 4; j++) acc[i][j] = 0.f;

    float4 ra = iv ? *(const float4*)(xrp + lq) : make_float4(0, 0, 0, 0);
    float4 rb = jv ? *(const float4*)(xlp + lq) : make_float4(0, 0, 0, 0);

    for (int k0 = 0; k0 < CC; k0 += 16) {
        As[lq + 0][lrow] = ra.x; As[lq + 1][lrow] = ra.y;
        As[lq + 2][lrow] = ra.z; As[lq + 3][lrow] = ra.w;
        Bs[lq + 0][lrow] = rb.x; Bs[lq + 1][lrow] = rb.y;
        Bs[lq + 2][lrow] = rb.z; Bs[lq + 3][lrow] = rb.w;
        __syncthreads();

        if (k0 + 16 < CC) {
            ra = iv ? *(const float4*)(xrp + k0 + 16 + lq) : make_float4(0, 0, 0, 0);
            rb = jv ? *(const float4*)(xlp + k0 + 16 + lq) : make_float4(0, 0, 0, 0);
        }

#pragma unroll
        for (int k = 0; k < 16; k++) {
            float4 a4 = *(const float4*)&As[k][ty << 2];
            float4 b4 = *(const float4*)&Bs[k][tx << 2];
            float av[4] = {a4.x, a4.y, a4.z, a4.w};
            float bv[4] = {b4.x, b4.y, b4.z, b4.w};
            float ac = att_s[k0 + k];
#pragma unroll
            for (int i = 0; i < 4; i++)
#pragma unroll
                for (int j = 0; j < 4; j++) {
                    float t = av[i] + bv[j];
                    acc[i][j] = fmaf(ac, fabsf(t), acc[i][j]);
                }
        }
        __syncthreads();
    }

#pragma unroll
    for (int ii = 0; ii < 4; ii++) {
        int i = i0 + (ty << 2) + ii;
        if (i >= NN) continue;
        float* row = g_S + (size_t)(h * NN + i) * NPJ;
#pragma unroll
        for (int jj = 0; jj < 4; jj++) {
            int j = j0 + (tx << 2) + jj;
            if (j < NN)
                row[j] = fmaf(0.4f, acc[ii][jj], 0.6f * AL_s[(tx << 2) + jj]);
        }
    }
}

// ---------------------------------------------------------------------------
// Fused segment-softmax + aggregation.
// ---------------------------------------------------------------------------
__global__ void __launch_bounds__(256) k_agg(const float* __restrict__ bias,
                                             int relu, int dst_sel) {
    float*    OUT  = dst_sel ? g_H2 : g_H;
    const int h    = blockIdx.y;
    const int i0   = blockIdx.x * 8;
    const int warp = threadIdx.x >> 5;
    const int lane = threadIdx.x & 31;

    __shared__ float  al[8][NPJ];
    __shared__ float4 xs[32][32];

    {
        int i = i0 + warp;
        if (i < NN) {
            const float* srow = g_S + (size_t)(h * NN + i) * NPJ;
            const int*   crow = g_cnt + i * NPJ;
            float sv[7], cv[7];
            float mx = -FLT_MAX;
#pragma unroll
            for (int t = 0; t < 7; t++) {
                int j = lane + t * 32;
                int c = (j < NN) ? crow[j] : 0;
                float s = (c > 0) ? srow[j] : -1e30f;
                sv[t] = s; cv[t] = (float)c;
                mx = fmaxf(mx, s);
            }
            for (int o = 16; o; o >>= 1) mx = fmaxf(mx, __shfl_xor_sync(0xffffffffu, mx, o));
            float ds = 0.f;
#pragma unroll
            for (int t = 0; t < 7; t++) ds += cv[t] * __expf(sv[t] - mx);
            for (int o = 16; o; o >>= 1) ds += __shfl_xor_sync(0xffffffffu, ds, o);
            float inv = 1.f / (ds + 1e-16f);
#pragma unroll
            for (int t = 0; t < 7; t++)
                al[warp][lane + t * 32] = cv[t] * __expf(sv[t] - mx) * inv;
        } else {
            for (int j = lane; j < NPJ; j += 32) al[warp][j] = 0.f;
        }
    }

    float4 acc = make_float4(0, 0, 0, 0);
    for (int j0 = 0; j0 < NN; j0 += 32) {
        __syncthreads();
        for (int idx = threadIdx.x; idx < 1024; idx += 256) {
            int jj = idx >> 5, cq = idx & 31;
            int j  = j0 + jj;
            xs[jj][cq] = (j < NN)
                ? *(const float4*)(g_XL + j * DD + (h << 7) + (cq << 2))
                : make_float4(0, 0, 0, 0);
        }
        __syncthreads();
#pragma unroll
        for (int jj = 0; jj < 32; jj++) {
            float  a = al[warp][j0 + jj];
            float4 x = xs[jj][lane];
            acc.x = fmaf(a, x.x, acc.x);
            acc.y = fmaf(a, x.y, acc.y);
            acc.z = fmaf(a, x.z, acc.z);
            acc.w = fmaf(a, x.w, acc.w);
        }
    }

    int i = i0 + warp;
    if (i < NN) {
        float4 bb = *(const float4*)(bias + (h << 7) + (lane << 2));
        float4 o;
        o.x = acc.x + bb.x; o.y = acc.y + bb.y;
        o.z = acc.z + bb.z; o.w = acc.w + bb.w;
        if (relu) {
            o.x = fmaxf(o.x, 0.f); o.y = fmaxf(o.y, 0.f);
            o.z = fmaxf(o.z, 0.f); o.w = fmaxf(o.w, 0.f);
        }
        *(float4*)(OUT + i * DD + (h << 7) + (lane << 2)) = o;
    }
}

// ---------------------------------------------------------------------------
__global__ void k_pool() {
    int d = blockIdx.x * blockDim.x + threadIdx.x;
    float s = 0.f;
    for (int i = 0; i < NN - 1; i++) s = fmaf(1.f / 300.f, g_H2[i * DD + d], s);
    s = fmaf(1.f / 3.f, g_H2[(NN - 1) * DD + d], s);
    g_avg[d] = s;
}

__global__ void k_clf(const float* __restrict__ W, const float* __restrict__ b,
                      float* __restrict__ out) {
    __shared__ float red0[8], red1[8];
    int tid = threadIdx.x;
    float p0 = 0.f, p1 = 0.f;
    for (int d = tid; d < DD; d += 256) {
        float a = g_avg[d];
        p0 = fmaf(a, W[d], p0);
        p1 = fmaf(a, W[DD + d], p1);
    }
    for (int o = 16; o; o >>= 1) {
        p0 += __shfl_xor_sync(0xffffffffu, p0, o);
        p1 += __shfl_xor_sync(0xffffffffu, p1, o);
    }
    if ((tid & 31) == 0) { red0[tid >> 5] = p0; red1[tid >> 5] = p1; }
    __syncthreads();
    if (tid == 0) {
        float s0 = 0.f, s1 = 0.f;
        for (int w = 0; w < 8; w++) { s0 += red0[w]; s1 += red1[w]; }
        out[0] = s0 + b[0];
        out[1] = s1 + b[1];
    }
}

// ---------------------------------------------------------------------------
extern "C" void kernel_launch(void* const* d_in, const int* in_sizes, int n_in,
                              void* d_out, int out_size) {
    const float* x     = (const float*)d_in[0];
    const int*   ebuf  = (const int*)  d_in[1];
    const float* W1l   = (const float*)d_in[2];
    const float* b1l   = (const float*)d_in[3];
    const float* W1r   = (const float*)d_in[4];
    const float* b1r   = (const float*)d_in[5];
    const float* att1  = (const float*)d_in[6];
    const float* bias1 = (const float*)d_in[7];
    const float* W2l   = (const float*)d_in[8];
    const float* b2l   = (const float*)d_in[9];
    const float* W2r   = (const float*)d_in[10];
    const float* b2r   = (const float*)d_in[11];
    const float* att2  = (const float*)d_in[12];
    const float* bias2 = (const float*)d_in[13];
    const float* clfW  = (const float*)d_in[14];
    const float* clfb  = (const float*)d_in[15];
    float* out = (float*)d_out;

    k_init <<<(NN * NPJ + 255) / 256, 256>>>(ebuf);
    k_count<<<(EE + 255) / 256, 256>>>(ebuf);

    dim3 gg(4, 16, 2);          // m-tiles x n-tiles x {l,r}
    dim3 gs(4, 4, HH);          // i-tiles x j-tiles x heads

    // layer 1
    k_gemm_mma<<<gg, 256>>>(x, W1l, b1l, W1r, b1r);
    k_score   <<<gs, 256>>>(att1);
    k_agg     <<<dim3(26, HH), 256>>>(bias1, /*relu=*/1, /*dst=*/0);

    // layer 2
    k_gemm_mma<<<gg, 256>>>(nullptr, W2l, b2l, W2r, b2r);
    k_score   <<<gs, 256>>>(att2);
    k_agg     <<<dim3(26, HH), 256>>>(bias2, /*relu=*/0, /*dst=*/1);

    // pooling + classifier
    k_pool<<<8, 128>>>();
    k_clf <<<1, 256>>>(clfW, clfb, out);
}

// round 5
// speedup vs baseline: 2.0241x; 1.1086x over previous
#include <cuda_runtime.h>
#include <cuda_bf16.h>
#include <mma.h>
#include <math.h>
#include <float.h>
#include <stdint.h>

using namespace nvcuda;

// ----------------------------------------------------------------------------
// GATv2 x2 + mean-pool + classifier, dense-pair formulation.
// N=201, E=40200 (+201 self loops), D=1024 = 8 heads x 128 ch.
// GEMMs: WMMA bf16 hi/lo split x3 (tcgen05 unavailable: harness targets sm_103).
// ----------------------------------------------------------------------------

#define NN   201
#define EE   40200
#define DD   1024
#define HH   8
#define CC   128
#define NPJ  224
#define NPAD 204

// -------- scratch (device globals; no allocation allowed) -------------------
__device__ __align__(16) float g_XL[NPAD * DD];
__device__ __align__(16) float g_XR[NPAD * DD];
__device__ __align__(16) float g_H [NPAD * DD];
__device__ __align__(16) float g_H2[NPAD * DD];
__device__ __align__(16) float g_S [HH * NN * NPJ];
__device__ int   g_cnt[NN * NPJ];
__device__ int   g_estride;

// ---------------------------------------------------------------------------
// init / edge count
// ---------------------------------------------------------------------------
__global__ void k_init(const int* __restrict__ eb) {
    int idx = blockIdx.x * blockDim.x + threadIdx.x;
    if (idx == 0) {
        int st = 2;  // assume int64 (low word = value, high word = 0)
        for (int e = 0; e < 64; e++)
            if (eb[2 * e + 1] != 0) { st = 1; break; }
        g_estride = st;
    }
    if (idx < NN * NPJ) {
        int r = idx / NPJ, c = idx - r * NPJ;
        g_cnt[idx] = (r == c && r < NN) ? 1 : 0;
    }
}

__global__ void k_count(const int* __restrict__ eb) {
    int e = blockIdx.x * blockDim.x + threadIdx.x;
    if (e < EE) {
        int st  = g_estride;
        int src = eb[e * st];
        int dst = eb[(EE + e) * st];
        atomicAdd(&g_cnt[dst * NPJ + src], 1);
    }
}

// ---------------------------------------------------------------------------
// WMMA bf16 GEMM, double-buffered: O[m][n] = sum_k X[m][k]*W[n][k] + b[n]
// CTA tile 64x64, K chunk 32, 2-deep smem pipeline, hi/lo split x3.
// grid = (4 m-tiles, 16 n-tiles, 2 sides); 256 threads (8 warps, 32x16 each).
// ---------------------------------------------------------------------------
#define A_LDM 40           // 32 k + 8 pad (bf16)
#define C_LDM 72           // 64 n + 8 pad (fp32)
#define BUF_ELEMS (4 * 64 * A_LDM)          // Ah|Al|Bh|Bl, one pipeline stage

__global__ void __launch_bounds__(256) k_gemm_mma(
    const float* __restrict__ Xin,
    const float* __restrict__ Wl, const float* __restrict__ bl,
    const float* __restrict__ Wr, const float* __restrict__ br)
{
    // 2 staging buffers (2*20480B) unioned with the fp32 epilogue tile (18432B)
    __shared__ __align__(16) char smem_raw[2 * BUF_ELEMS * 2];

    const float* X = Xin ? Xin : g_H;
    const int side = blockIdx.z;
    const float* W = side ? Wr : Wl;
    const float* b = side ? br : bl;
    float*       O = side ? g_XR : g_XL;
    const int m0 = blockIdx.x * 64;
    const int n0 = blockIdx.y * 64;

    const int tid  = threadIdx.x;
    const int wid  = tid >> 5;
    const int wm   = wid >> 2;        // 0..1 -> m offset 0/32
    const int wn   = wid & 3;         // 0..3 -> n offset 0/16/32/48

    wmma::fragment<wmma::accumulator, 16, 16, 16, float> c0, c1;
    wmma::fill_fragment(c0, 0.f);
    wmma::fill_fragment(c1, 0.f);

    // loader mapping: 4 threads per row, 8 k-elements each
    const int  lr = tid >> 2;
    const int  lq = (tid & 3) * 8;
    const bool av = (m0 + lr) < NN;
    const float* arow = X + (size_t)(m0 + lr) * DD + lq;
    const float* brow = W + (size_t)(n0 + lr) * DD + lq;

    // helper lambda-ish macros via inline code
    auto stage = [&](int buf, float4 a0, float4 a1, float4 b0, float4 b1) {
        __nv_bfloat16* Ah = (__nv_bfloat16*)smem_raw + buf * BUF_ELEMS;
        __nv_bfloat16* Al = Ah + 64 * A_LDM;
        __nv_bfloat16* Bh = Al + 64 * A_LDM;
        __nv_bfloat16* Bl = Bh + 64 * A_LDM;
        float va[8] = {a0.x, a0.y, a0.z, a0.w, a1.x, a1.y, a1.z, a1.w};
        float vb[8] = {b0.x, b0.y, b0.z, b0.w, b1.x, b1.y, b1.z, b1.w};
        __nv_bfloat16 hi[8], lo[8];
#pragma unroll
        for (int e = 0; e < 8; e++) {
            hi[e] = __float2bfloat16(va[e]);
            lo[e] = __float2bfloat16(va[e] - __bfloat162float(hi[e]));
        }
        *(uint4*)(Ah + lr * A_LDM + lq) = *(uint4*)hi;
        *(uint4*)(Al + lr * A_LDM + lq) = *(uint4*)lo;
#pragma unroll
        for (int e = 0; e < 8; e++) {
            hi[e] = __float2bfloat16(vb[e]);
            lo[e] = __float2bfloat16(vb[e] - __bfloat162float(hi[e]));
        }
        *(uint4*)(Bh + lr * A_LDM + lq) = *(uint4*)hi;
        *(uint4*)(Bl + lr * A_LDM + lq) = *(uint4*)lo;
    };

    // prologue: stage chunk 0
    {
        float4 a0 = av ? *(const float4*)(arow)     : make_float4(0, 0, 0, 0);
        float4 a1 = av ? *(const float4*)(arow + 4) : make_float4(0, 0, 0, 0);
        float4 b0 = *(const float4*)(brow);
        float4 b1 = *(const float4*)(brow + 4);
        stage(0, a0, a1, b0, b1);
    }
    __syncthreads();

    const int NCHUNK = DD / 32;
    for (int kc = 0; kc < NCHUNK; kc++) {
        const int cur = kc & 1;

        // issue global prefetch for next chunk early
        float4 a0, a1, b0, b1;
        const bool more = (kc + 1 < NCHUNK);
        if (more) {
            const int kb = (kc + 1) * 32;
            a0 = av ? *(const float4*)(arow + kb)     : make_float4(0, 0, 0, 0);
            a1 = av ? *(const float4*)(arow + kb + 4) : make_float4(0, 0, 0, 0);
            b0 = *(const float4*)(brow + kb);
            b1 = *(const float4*)(brow + kb + 4);
        }

        // compute on current buffer
        {
            __nv_bfloat16* Ah = (__nv_bfloat16*)smem_raw + cur * BUF_ELEMS;
            __nv_bfloat16* Al = Ah + 64 * A_LDM;
            __nv_bfloat16* Bh = Al + 64 * A_LDM;
            __nv_bfloat16* Bl = Bh + 64 * A_LDM;
#pragma unroll
            for (int ks = 0; ks < 2; ks++) {
                const int kk = ks * 16;
                wmma::fragment<wmma::matrix_b, 16, 16, 16, __nv_bfloat16, wmma::col_major> fbh, fbl;
                wmma::load_matrix_sync(fbh, Bh + (wn * 16) * A_LDM + kk, A_LDM);
                wmma::load_matrix_sync(fbl, Bl + (wn * 16) * A_LDM + kk, A_LDM);

                wmma::fragment<wmma::matrix_a, 16, 16, 16, __nv_bfloat16, wmma::row_major> fah, fal;
                wmma::load_matrix_sync(fah, Ah + (wm * 32) * A_LDM + kk, A_LDM);
                wmma::load_matrix_sync(fal, Al + (wm * 32) * A_LDM + kk, A_LDM);
                wmma::mma_sync(c0, fah, fbh, c0);
                wmma::mma_sync(c0, fah, fbl, c0);
                wmma::mma_sync(c0, fal, fbh, c0);
                wmma::load_matrix_sync(fah, Ah + (wm * 32 + 16) * A_LDM + kk, A_LDM);
                wmma::load_matrix_sync(fal, Al + (wm * 32 + 16) * A_LDM + kk, A_LDM);
                wmma::mma_sync(c1, fah, fbh, c1);
                wmma::mma_sync(c1, fah, fbl, c1);
                wmma::mma_sync(c1, fal, fbh, c1);
            }
        }

        // store prefetched chunk into the other buffer
        if (more) stage(cur ^ 1, a0, a1, b0, b1);
        __syncthreads();
    }

    // ---- epilogue via smem (aliases staging buffers), fused bias ----
    float* Cs = (float*)smem_raw;
    wmma::store_matrix_sync(Cs + (wm * 32) * C_LDM + wn * 16, c0, C_LDM, wmma::mem_row_major);
    wmma::store_matrix_sync(Cs + (wm * 32 + 16) * C_LDM + wn * 16, c1, C_LDM, wmma::mem_row_major);
    __syncthreads();

    const int m = m0 + lr;
    if (m < NN) {
        const int cb = (tid & 3) * 16;
        float* orow = O + (size_t)m * DD + n0 + cb;
        const float* bp = b + n0 + cb;
#pragma unroll
        for (int c4 = 0; c4 < 16; c4 += 4) {
            float4 vv = *(float4*)&Cs[lr * C_LDM + cb + c4];
            float4 bb = *(const float4*)(bp + c4);
            vv.x += bb.x; vv.y += bb.y; vv.z += bb.z; vv.w += bb.w;
            *(float4*)(orow + c4) = vv;
        }
    }
}

// ---------------------------------------------------------------------------
// Dense pairwise scores, 32x32 tiles / 128 threads for high occupancy.
//   S[h,i,j] = 0.4 * sum_c att|xl_j + xr_i| + 0.6*AL[j]   (AR term cancels)
// grid = (7 i-tiles, 7 j-tiles, 8 heads) = 392 blocks.
// Thread microtile 2i x 4j: ty = tid>>3 (16), tx = tid&7 (8).
// ---------------------------------------------------------------------------
__global__ void __launch_bounds__(128) k_score(const float* __restrict__ att) {
    const int h   = blockIdx.z;
    const int i0  = blockIdx.x * 32;
    const int j0  = blockIdx.y * 32;
    const int tid = threadIdx.x;
    const int tx  = tid & 7;
    const int ty  = tid >> 3;
    const int lrow = tid >> 2;        // 0..31 staging row
    const int lq   = (tid & 3) << 2;  // k offset 0,4,8,12

    __shared__ __align__(16) float att_s[CC];
    __shared__ float AL_s[32];
    __shared__ float alp[32][4];
    __shared__ float As[16][32];   // xr chunk [k][i]
    __shared__ float Bs[16][32];   // xl chunk [k][j]

    if (tid < 32) *(float4*)&att_s[tid * 4] = *(const float4*)(att + h * CC + tid * 4);
    __syncthreads();

    // AL[j]: 4 threads per j, 32 channels each
    {
        int jj = tid >> 2, part = tid & 3;
        int j  = j0 + jj;
        float s = 0.f;
        if (j < NN) {
            const float4* xp4 = (const float4*)(g_XL + j * DD + h * CC + part * 32);
#pragma unroll
            for (int q = 0; q < 8; q++) {
                float4 xv = xp4[q];
                const float* ap = att_s + part * 32 + q * 4;
                s = fmaf(ap[0], xv.x, s);
                s = fmaf(ap[1], xv.y, s);
                s = fmaf(ap[2], xv.z, s);
                s = fmaf(ap[3], xv.w, s);
            }
        }
        alp[jj][part] = s;
    }
    __syncthreads();
    if (tid < 32) AL_s[tid] = alp[tid][0] + alp[tid][1] + alp[tid][2] + alp[tid][3];
    __syncthreads();

    const int  gi = i0 + lrow;
    const int  gj = j0 + lrow;
    const bool iv = (gi < NN);
    const bool jv = (gj < NN);
    const float* xrp = g_XR + gi * DD + h * CC;
    const float* xlp = g_XL + gj * DD + h * CC;

    float acc[2][4];
#pragma unroll
    for (int i = 0; i < 2; i++)
#pragma unroll
        for (int j = 0; j < 4; j++) acc[i][j] = 0.f;

    float4 ra = iv ? *(const float4*)(xrp + lq) : make_float4(0, 0, 0, 0);
    float4 rb = jv ? *(const float4*)(xlp + lq) : make_float4(0, 0, 0, 0);

    for (int k0 = 0; k0 < CC; k0 += 16) {
        As[lq + 0][lrow] = ra.x; As[lq + 1][lrow] = ra.y;
        As[lq + 2][lrow] = ra.z; As[lq + 3][lrow] = ra.w;
        Bs[lq + 0][lrow] = rb.x; Bs[lq + 1][lrow] = rb.y;
        Bs[lq + 2][lrow] = rb.z; Bs[lq + 3][lrow] = rb.w;
        __syncthreads();

        if (k0 + 16 < CC) {
            ra = iv ? *(const float4*)(xrp + k0 + 16 + lq) : make_float4(0, 0, 0, 0);
            rb = jv ? *(const float4*)(xlp + k0 + 16 + lq) : make_float4(0, 0, 0, 0);
        }

#pragma unroll
        for (int k = 0; k < 16; k++) {
            float a0 = As[k][ty * 2 + 0];
            float a1 = As[k][ty * 2 + 1];
            float4 b4 = *(const float4*)&Bs[k][tx << 2];
            float bv[4] = {b4.x, b4.y, b4.z, b4.w};
            float ac = att_s[k0 + k];
#pragma unroll
            for (int j = 0; j < 4; j++) {
                float t0 = a0 + bv[j];
                float t1 = a1 + bv[j];
                acc[0][j] = fmaf(ac, fabsf(t0), acc[0][j]);
                acc[1][j] = fmaf(ac, fabsf(t1), acc[1][j]);
            }
        }
        __syncthreads();
    }

#pragma unroll
    for (int ii = 0; ii < 2; ii++) {
        int i = i0 + ty * 2 + ii;
        if (i >= NN) continue;
        float* row = g_S + (size_t)(h * NN + i) * NPJ;
#pragma unroll
        for (int jj = 0; jj < 4; jj++) {
            int j = j0 + (tx << 2) + jj;
            if (j < NN)
                row[j] = fmaf(0.4f, acc[ii][jj], 0.6f * AL_s[(tx << 2) + jj]);
        }
    }
}

// ---------------------------------------------------------------------------
// Fused segment-softmax + aggregation.
// Block = (i-tile of 8, head). Warp w owns destination row i0+w.
// ---------------------------------------------------------------------------
__global__ void __launch_bounds__(256) k_agg(const float* __restrict__ bias,
                                             int relu, int dst_sel) {
    float*    OUT  = dst_sel ? g_H2 : g_H;
    const int h    = blockIdx.y;
    const int i0   = blockIdx.x * 8;
    const int warp = threadIdx.x >> 5;
    const int lane = threadIdx.x & 31;

    __shared__ float  al[8][NPJ];
    __shared__ float4 xs[32][32];

    {
        int i = i0 + warp;
        if (i < NN) {
            const float* srow = g_S + (size_t)(h * NN + i) * NPJ;
            const int*   crow = g_cnt + i * NPJ;
            float sv[7], cv[7];
            float mx = -FLT_MAX;
#pragma unroll
            for (int t = 0; t < 7; t++) {
                int j = lane + t * 32;
                int c = (j < NN) ? crow[j] : 0;
                float s = (c > 0) ? srow[j] : -1e30f;
                sv[t] = s; cv[t] = (float)c;
                mx = fmaxf(mx, s);
            }
            for (int o = 16; o; o >>= 1) mx = fmaxf(mx, __shfl_xor_sync(0xffffffffu, mx, o));
            float ds = 0.f;
#pragma unroll
            for (int t = 0; t < 7; t++) ds += cv[t] * __expf(sv[t] - mx);
            for (int o = 16; o; o >>= 1) ds += __shfl_xor_sync(0xffffffffu, ds, o);
            float inv = 1.f / (ds + 1e-16f);
#pragma unroll
            for (int t = 0; t < 7; t++)
                al[warp][lane + t * 32] = cv[t] * __expf(sv[t] - mx) * inv;
        } else {
            for (int j = lane; j < NPJ; j += 32) al[warp][j] = 0.f;
        }
    }

    float4 acc = make_float4(0, 0, 0, 0);
    for (int j0 = 0; j0 < NN; j0 += 32) {
        __syncthreads();
        for (int idx = threadIdx.x; idx < 1024; idx += 256) {
            int jj = idx >> 5, cq = idx & 31;
            int j  = j0 + jj;
            xs[jj][cq] = (j < NN)
                ? *(const float4*)(g_XL + j * DD + (h << 7) + (cq << 2))
                : make_float4(0, 0, 0, 0);
        }
        __syncthreads();
#pragma unroll
        for (int jj = 0; jj < 32; jj++) {
            float  a = al[warp][j0 + jj];
            float4 x = xs[jj][lane];
            acc.x = fmaf(a, x.x, acc.x);
            acc.y = fmaf(a, x.y, acc.y);
            acc.z = fmaf(a, x.z, acc.z);
            acc.w = fmaf(a, x.w, acc.w);
        }
    }

    int i = i0 + warp;
    if (i < NN) {
        float4 bb = *(const float4*)(bias + (h << 7) + (lane << 2));
        float4 o;
        o.x = acc.x + bb.x; o.y = acc.y + bb.y;
        o.z = acc.z + bb.z; o.w = acc.w + bb.w;
        if (relu) {
            o.x = fmaxf(o.x, 0.f); o.y = fmaxf(o.y, 0.f);
            o.z = fmaxf(o.z, 0.f); o.w = fmaxf(o.w, 0.f);
        }
        *(float4*)(OUT + i * DD + (h << 7) + (lane << 2)) = o;
    }
}

// ---------------------------------------------------------------------------
// Fused pooling + classifier (one block, 1024 threads).
// avg[d] = sum_{i<200} H2[i][d]/300 + H2[200][d]/3 ; out = avg @ W^T + b
// ---------------------------------------------------------------------------
__global__ void __launch_bounds__(1024) k_poolclf(const float* __restrict__ W,
                                                  const float* __restrict__ b,
                                                  float* __restrict__ out) {
    __shared__ float avg_s[DD];
    __shared__ float red0[32], red1[32];
    const int d = threadIdx.x;

    float s = 0.f;
    for (int i = 0; i < 200; i++) s += g_H2[i * DD + d];
    s = s * (1.f / 300.f) + g_H2[200 * DD + d] * (1.f / 3.f);
    avg_s[d] = s;
    __syncthreads();

    float p0 = s * W[d];
    float p1 = s * W[DD + d];
    for (int o = 16; o; o >>= 1) {
        p0 += __shfl_xor_sync(0xffffffffu, p0, o);
        p1 += __shfl_xor_sync(0xffffffffu, p1, o);
    }
    if ((d & 31) == 0) { red0[d >> 5] = p0; red1[d >> 5] = p1; }
    __syncthreads();
    if (d == 0) {
        float s0 = 0.f, s1 = 0.f;
        for (int w = 0; w < 32; w++) { s0 += red0[w]; s1 += red1[w]; }
        out[0] = s0 + b[0];
        out[1] = s1 + b[1];
    }
}

// ---------------------------------------------------------------------------
extern "C" void kernel_launch(void* const* d_in, const int* in_sizes, int n_in,
                              void* d_out, int out_size) {
    const float* x     = (const float*)d_in[0];
    const int*   ebuf  = (const int*)  d_in[1];
    const float* W1l   = (const float*)d_in[2];
    const float* b1l   = (const float*)d_in[3];
    const float* W1r   = (const float*)d_in[4];
    const float* b1r   = (const float*)d_in[5];
    const float* att1  = (const float*)d_in[6];
    const float* bias1 = (const float*)d_in[7];
    const float* W2l   = (const float*)d_in[8];
    const float* b2l   = (const float*)d_in[9];
    const float* W2r   = (const float*)d_in[10];
    const float* b2r   = (const float*)d_in[11];
    const float* att2  = (const float*)d_in[12];
    const float* bias2 = (const float*)d_in[13];
    const float* clfW  = (const float*)d_in[14];
    const float* clfb  = (const float*)d_in[15];
    float* out = (float*)d_out;

    k_init <<<(NN * NPJ + 255) / 256, 256>>>(ebuf);
    k_count<<<(EE + 255) / 256, 256>>>(ebuf);

    dim3 gg(4, 16, 2);          // m-tiles x n-tiles x {l,r}
    dim3 gs(7, 7, HH);          // i-tiles x j-tiles x heads (392 blocks)

    // layer 1
    k_gemm_mma<<<gg, 256>>>(x, W1l, b1l, W1r, b1r);
    k_score   <<<gs, 128>>>(att1);
    k_agg     <<<dim3(26, HH), 256>>>(bias1, /*relu=*/1, /*dst=*/0);

    // layer 2
    k_gemm_mma<<<gg, 256>>>(nullptr, W2l, b2l, W2r, b2r);
    k_score   <<<gs, 128>>>(att2);
    k_agg     <<<dim3(26, HH), 256>>>(bias2, /*relu=*/0, /*dst=*/1);

    // fused pooling + classifier
    k_poolclf<<<1, 1024>>>(clfW, clfb, out);
}